// round 1
// baseline (speedup 1.0000x reference)
#include <cuda_runtime.h>
#include <math_constants.h>

// Problem constants
#define NLAG   12          // LAG-1
#define NB     32          // batch
#define NN     1200        // N
#define MROWS  1152        // 3 * NLAG * NB
#define KDIM   1200

// Scratch (no allocations allowed)
__device__ float g_X[MROWS * KDIM];   // packed GEMM A operand
__device__ float g_C[MROWS * NN];     // tanh(-X @ WW)
__device__ float g_belta[NLAG];
__device__ float g_c2[NLAG];
__device__ float g_pf[NLAG];

__device__ __forceinline__ float gamma_fn(float x) {
    if (x > 0.f) return expf(lgammaf(x));
    return CUDART_PI_F / (sinf(CUDART_PI_F * x) * expf(lgammaf(1.f - x)));
}

// ---------------------------------------------------------------------------
// Per-lag scalars (12 of them): belta, c2, pf = 2*3^fract
// ---------------------------------------------------------------------------
__global__ void scalars_kernel(const float* __restrict__ alpha,
                               const float* __restrict__ fract) {
    int lag = threadIdx.x;
    if (lag >= NLAG) return;
    float a   = alpha[lag];
    float f   = fract[lag];
    float ga1 = gamma_fn(a + 1.f);
    float gm2 = gamma_fn(a - 2.f);
    float belta = ga1 / gamma_fn(a + 1.f)          // kk=0: 0!=1
                + ga1 / gamma_fn(a)                // kk=1: 1!=1
                + ga1 / (2.f * gamma_fn(a - 1.f))  // kk=2: 2!=2
                + ga1 / (6.f * gm2);               // kk=3: 3!=6
    g_belta[lag] = belta;
    g_c2[lag]    = ga1 / (6.f * gm2);
    g_pf[lag]    = 2.f * powf(3.f, f);             // 2 / H^fract, H=1/3
}

// ---------------------------------------------------------------------------
// Pack the three GEMM-A operands into one contiguous 1152 x 1200 matrix:
// rows [0,384)    : A[lag,b,i]                     (contiguous input)
// rows [384,768)  : train_init[b,i,lag+1,1]        (A_0_NEW source)
// rows [768,1152) : train_init[b,i,lag,  1]        (A_N_OLD source)
// ---------------------------------------------------------------------------
__global__ void pack_kernel(const float* __restrict__ A,
                            const float* __restrict__ train_init) {
    int idx = blockIdx.x * blockDim.x + threadIdx.x;
    if (idx >= MROWS * KDIM) return;
    int r = idx / KDIM;
    int i = idx - r * KDIM;
    float v;
    if (r < 384) {
        v = A[idx];
    } else {
        int rr  = r - 384;
        int mat = rr / 384;          // 0 -> lag+1 slice, 1 -> lag slice
        rr      = rr % 384;
        int lag = rr / NB;
        int b   = rr % NB;
        int lagidx = (mat == 0) ? (lag + 1) : lag;
        v = train_init[((b * NN + i) * 13 + lagidx) * 2 + 1];
    }
    g_X[idx] = v;
}

// ---------------------------------------------------------------------------
// Tiled fp32 GEMM: C = tanh(-(X @ WW)),  X:[1152,1200], WW:[1200,1200]
// BM=BN=64, BK=16, 256 threads, 4x4 per thread.
// ---------------------------------------------------------------------------
#define BM 64
#define BN 64
#define BK 16

__global__ __launch_bounds__(256, 4)
void gemm_tanh_kernel(const float* __restrict__ Bmat) {
    __shared__ float As[BK][BM];       // stored k-major for float4 reads
    __shared__ float Bs[BK][BN];

    const int tid = threadIdx.x;
    const int m0  = blockIdx.y * BM;
    const int n0  = blockIdx.x * BN;
    const int ty  = tid >> 4;          // 0..15
    const int tx  = tid & 15;          // 0..15

    // A-tile loader: 64 rows x 16 k, float4 per thread
    const int arow  = tid >> 2;            // 0..63
    const int akcol = (tid & 3) << 2;      // 0,4,8,12
    // B-tile loader: 16 k x 64 n, float4 per thread
    const int brow  = tid >> 4;            // 0..15
    const int bcol  = (tid & 15) << 2;     // 0..60

    float acc[4][4];
#pragma unroll
    for (int i = 0; i < 4; i++)
#pragma unroll
        for (int j = 0; j < 4; j++) acc[i][j] = 0.f;

    const bool bvalid = (n0 + bcol) < NN;

    for (int k0 = 0; k0 < KDIM; k0 += BK) {
        float4 av = *reinterpret_cast<const float4*>(
            &g_X[(m0 + arow) * KDIM + k0 + akcol]);
        As[akcol + 0][arow] = av.x;
        As[akcol + 1][arow] = av.y;
        As[akcol + 2][arow] = av.z;
        As[akcol + 3][arow] = av.w;

        float4 bv = make_float4(0.f, 0.f, 0.f, 0.f);
        if (bvalid)
            bv = *reinterpret_cast<const float4*>(
                &Bmat[(k0 + brow) * NN + n0 + bcol]);
        *reinterpret_cast<float4*>(&Bs[brow][bcol]) = bv;

        __syncthreads();

#pragma unroll
        for (int k = 0; k < BK; k++) {
            float4 ra = *reinterpret_cast<const float4*>(&As[k][ty << 2]);
            float4 rb = *reinterpret_cast<const float4*>(&Bs[k][tx << 2]);
            float a0 = ra.x, a1 = ra.y, a2 = ra.z, a3 = ra.w;
            float b0 = rb.x, b1 = rb.y, b2 = rb.z, b3 = rb.w;
            acc[0][0] += a0 * b0; acc[0][1] += a0 * b1; acc[0][2] += a0 * b2; acc[0][3] += a0 * b3;
            acc[1][0] += a1 * b0; acc[1][1] += a1 * b1; acc[1][2] += a1 * b2; acc[1][3] += a1 * b3;
            acc[2][0] += a2 * b0; acc[2][1] += a2 * b1; acc[2][2] += a2 * b2; acc[2][3] += a2 * b3;
            acc[3][0] += a3 * b0; acc[3][1] += a3 * b1; acc[3][2] += a3 * b2; acc[3][3] += a3 * b3;
        }
        __syncthreads();
    }

#pragma unroll
    for (int i = 0; i < 4; i++) {
        int row = m0 + (ty << 2) + i;
#pragma unroll
        for (int j = 0; j < 4; j++) {
            int col = n0 + (tx << 2) + j;
            if (col < NN) g_C[row * NN + col] = tanhf(-acc[i][j]);
        }
    }
}

// ---------------------------------------------------------------------------
// Epilogue: out[b,lag,j] = lambd/belta * ( pf*OUT + 3*l*(A0NEW + c2*ANOLD) )
// ---------------------------------------------------------------------------
__global__ void epilogue_kernel(const float* __restrict__ lambd,
                                const float* __restrict__ l,
                                float* __restrict__ out) {
    int idx = blockIdx.x * blockDim.x + threadIdx.x;
    const int total = NB * NLAG * NN;
    if (idx >= total) return;
    int j   = idx % NN;
    int lag = (idx / NN) % NLAG;
    int b   = idx / (NN * NLAG);
    int jm  = j % 200;

    int r = lag * NB + b;
    float outv = g_C[r * NN + j];
    float a0   = g_C[(384 + r) * NN + j];
    float an   = g_C[(768 + r) * NN + j];

    float lam = lambd[lag * 200 + jm];
    float lv  = l[lag * 200 + jm];

    out[idx] = lam / g_belta[lag] *
               (g_pf[lag] * outv + 3.f * lv * (a0 + g_c2[lag] * an));
}

// ---------------------------------------------------------------------------
extern "C" void kernel_launch(void* const* d_in, const int* in_sizes, int n_in,
                              void* d_out, int out_size) {
    const float* A          = (const float*)d_in[0];  // (12,32,1200,1)
    const float* WW         = (const float*)d_in[1];  // (1200,1200,1)
    const float* train_init = (const float*)d_in[2];  // (32,1200,13,2)
    const float* alpha      = (const float*)d_in[3];  // (12,1)
    const float* fract      = (const float*)d_in[4];  // (12,1)
    const float* lambd      = (const float*)d_in[5];  // (12,1,200,1)
    const float* l          = (const float*)d_in[6];  // (12,1,200,1)
    // d_in[7] (A_y_list) is dead: index 0 overwritten before use, binom0 == 1
    float* out = (float*)d_out;

    scalars_kernel<<<1, 32>>>(alpha, fract);

    const int packN = MROWS * KDIM;
    pack_kernel<<<(packN + 255) / 256, 256>>>(A, train_init);

    dim3 grid((NN + BN - 1) / BN, MROWS / BM);  // (19, 18)
    gemm_tanh_kernel<<<grid, 256>>>(WW);

    const int total = NB * NLAG * NN;
    epilogue_kernel<<<(total + 255) / 256, 256>>>(lambd, l, out);
}